// round 4
// baseline (speedup 1.0000x reference)
#include <cuda_runtime.h>

#define TN 400
#define PN 4000
#define NBLOCKS 152       // one block per GB300 SM
#define TPB 832           // 26 warps; warps 0..24 own 16 targets each
#define MAXP 28           // >= ceil(PN/NBLOCKS)+1

typedef unsigned long long ull;

// ---- packed f32x2 helpers (sm_103a double-rate fp32) ----
__device__ __forceinline__ ull pk2(float lo, float hi) {
    ull r; asm("mov.b64 %0, {%1,%2};" : "=l"(r) : "f"(lo), "f"(hi)); return r;
}
__device__ __forceinline__ float2 u2f2(ull v) {
    float2 f; asm("mov.b64 {%0,%1}, %2;" : "=f"(f.x), "=f"(f.y) : "l"(v)); return f;
}
__device__ __forceinline__ ull padd2(ull a, ull b) {
    ull r; asm("add.rn.f32x2 %0, %1, %2;" : "=l"(r) : "l"(a), "l"(b)); return r;
}
__device__ __forceinline__ ull pfma2(ull a, ull b, ull c) {
    ull r; asm("fma.rn.f32x2 %0, %1, %2, %3;" : "=l"(r) : "l"(a), "l"(b), "l"(c)); return r;
}

#define NINE2  0x4110000041100000ULL   // {9.0f, 9.0f}
#define SEVEN2 0x40E0000040E00000ULL   // {7.0f, 7.0f}

// ptile row layout (64 floats per pred):
//  [ 0..33] Zp pairs (x,y per keypoint)   [34..35] zero pad (read by half1 i=8)
//  [36..39] {cp0, cp1, p0-p1, spp}
//  [40..48] Vp[0..8]   [49..51] pad
//  [52..59] Vp[9..16]  [60] zero pad (read by half1 i=8)  [61..63] pad

__global__ __launch_bounds__(TPB, 1)
void matcher_kernel(const float* __restrict__ logits,   // [PN,2]
                    const float* __restrict__ pkp,      // [PN,53]
                    const int*   __restrict__ tids,     // [TN]
                    const float* __restrict__ tkp,      // [TN,53]
                    const int*   __restrict__ nbp,      // scalar num_boxes
                    float*       __restrict__ out)      // [PN,TN]
{
    __shared__ __align__(16) float ptile[MAXP * 64];

    const int b = blockIdx.x;
    const int pbase = (b * PN) / NBLOCKS;
    const int npred = ((b + 1) * PN) / NBLOCKS - pbase;
    const int tid  = threadIdx.x;
    const int wr   = tid >> 5;
    const int lane = tid & 31;
    const int h    = lane >> 4;                 // keypoint half: 0 -> kp 0..8, 1 -> kp 9..16
    const int cnt  = h ? 8 : 9;
    const int jb   = h ? 9 : 0;
    int  tw  = (wr << 4) | (lane & 15);         // this thread's target
    const bool act = (tw < TN);
    if (!act) tw = 0;

    int nbi = *nbp;
    float nb = (nbi > 0 && nbi < (1 << 20)) ? (float)nbi : *(const float*)nbp;
    const float inb = 1.0f / nb;

    // ---- pred preprocessing into shared (threads 0..npred-1, once) ----
    if (tid < npred) {
        const int gp = pbase + tid;
        const float l0 = logits[gp * 2 + 0];
        const float l1 = logits[gp * 2 + 1];
        const float m  = fmaxf(l0, l1);
        const float e0 = __expf(l0 - m);
        const float e1 = __expf(l1 - m);
        const float inv = 1.0f / (e0 + e1);
        const float p0 = e0 * inv, p1 = e1 * inv;

        const float* kp = pkp + gp * 53;
        const float c0 = kp[0], c1 = kp[1];
        float* sp = ptile + tid * 64;
        #pragma unroll
        for (int k = 0; k < 34; ++k) sp[k] = kp[2 + k];       // Zp
        sp[34] = 0.0f; sp[35] = 0.0f;
        float sv = 0.0f;
        #pragma unroll
        for (int j = 0; j < 17; ++j) {
            float v = kp[36 + j];
            sv = fmaf(v, v, sv);
        }
        sp[36] = c0;
        sp[37] = c1;
        sp[38] = p0 - p1;
        sp[39] = 0.2f * inb * sv + 0.5f * inb * (c0 * c0 + c1 * c1) - p0;  // spp
        #pragma unroll
        for (int j = 0; j < 9; ++j)  sp[40 + j] = kp[36 + j];      // Vp[0..8]
        sp[49] = 0.0f; sp[50] = 0.0f; sp[51] = 0.0f;
        #pragma unroll
        for (int j = 0; j < 8; ++j)  sp[52 + j] = kp[45 + j];      // Vp[9..16]
        sp[60] = 0.0f; sp[61] = 0.0f; sp[62] = 0.0f; sp[63] = 0.0f;
    }

    // ---- per-thread target state: 9 keypoints of one target, in registers ----
    ull   nzg[9];
    float w[9];
    float ng8x = 0.0f, ng8y = 0.0f;
    float tcx = 0.0f, tcy = 0.0f, idf = 0.0f, sgt = 0.0f, cflag = 0.0f;
    {
        const float* tk = tkp + tw * 53;
        const float c0 = tk[0], c1 = tk[1];
        #pragma unroll
        for (int i = 0; i < 9; ++i) {
            const int j = jb + i;
            const bool ok = act && (i < cnt);
            nzg[i] = ok ? pk2(-tk[2 + 2 * j], -tk[3 + 2 * j]) : 0ULL;
            w[i]   = ok ? 0.5f * inb * tk[36 + j] : 0.0f;
        }
        if (act) {
            ng8x = -8.0f * c0;
            ng8y = -8.0f * c1;
            if (h == 0) {
                float sv = 0.0f;
                #pragma unroll
                for (int j = 0; j < 17; ++j) { float v = tk[36 + j]; sv = fmaf(v, v, sv); }
                sgt = 0.2f * inb * sv + 0.5f * inb * (c0 * c0 + c1 * c1);
                tcx = -inb * c0;
                tcy = -inb * c1;
                idf = (float)tids[tw];
                cflag = 1.0f;      // multiplies spp (pred constant), half0 only
            }
        }
    }
    __syncthreads();

    const bool doStore = act && (h == 0);

    // ---- main loop over this block's preds ----
    for (int p = 0; p < npred; ++p) {
        const float* pp = ptile + p * 64;
        const float4 h4 = *(const float4*)(pp + 36);   // cp0, cp1, p0-p1, spp
        const ull hp = pk2(fmaf(h4.x, 8.0f, ng8x), fmaf(h4.y, 8.0f, ng8y));

        const ull* zbase = (const ull*)pp + jb;        // keypoint j at ull index j
        float s0 = 0.0f, s1 = 0.0f;
        #pragma unroll
        for (int i = 0; i < 9; ++i) {
            ull z  = zbase[i];                          // half-warp broadcast LDS.64
            ull dz = padd2(z, nzg[i]);
            ull u1 = pfma2(dz, NINE2,  hp);
            ull u2 = pfma2(dz, SEVEN2, hp);
            float2 a = u2f2(u1), c = u2f2(u2);
            float mx = fmaxf(fabsf(a.x), fabsf(c.x));
            float my = fmaxf(fabsf(a.y), fabsf(c.y));
            s0 = fmaf(mx, w[i], s0);
            s1 = fmaf(my, w[i], s1);
        }

        // viz dot: 9 Vp values for this half (half1 slot 8 is zero pad)
        const float* vb = pp + 40 + h * 12;
        const float4 v0 = *(const float4*)vb;
        const float4 v1 = *(const float4*)(vb + 4);
        const float  v8 = vb[8];
        float dv = v0.x * w[0];
        dv = fmaf(v0.y, w[1], dv); dv = fmaf(v0.z, w[2], dv);
        dv = fmaf(v0.w, w[3], dv); dv = fmaf(v1.x, w[4], dv);
        dv = fmaf(v1.y, w[5], dv); dv = fmaf(v1.z, w[6], dv);
        dv = fmaf(v1.w, w[7], dv); dv = fmaf(v8,   w[8], dv);

        float res = s0 + s1;
        res = fmaf(dv, -0.8f, res);
        res = fmaf(h4.x, tcx, res);        // center cross x   (half0 only, 0 else)
        res = fmaf(h4.y, tcy, res);        // center cross y
        res = fmaf(h4.z, idf, res);        // class id*(p0-p1)
        res = fmaf(h4.w, cflag, res);      // pred constant (incl -p0)
        res += sgt;                        // target constant

        res += __shfl_xor_sync(0xffffffffu, res, 16);

        if (doStore)
            out[(size_t)(pbase + p) * TN + tw] = res;
    }
}

extern "C" void kernel_launch(void* const* d_in, const int* in_sizes, int n_in,
                              void* d_out, int out_size)
{
    const float* logits = (const float*)d_in[0];   // pred_logits   [8,500,2]
    const float* pkp    = (const float*)d_in[1];   // pred_keypoints[8,500,53]
    const int*   tids   = (const int*)  d_in[2];   // tgt_ids       [400]
    const float* tkp    = (const float*)d_in[3];   // tgt_keypoints [400,53]
    const int*   nbp    = (const int*)  d_in[4];   // num_boxes scalar
    (void)in_sizes; (void)n_in; (void)out_size;

    matcher_kernel<<<NBLOCKS, TPB>>>(logits, pkp, tids, tkp, nbp, (float*)d_out);
}

// round 5
// speedup vs baseline: 1.1761x; 1.1761x over previous
#include <cuda_runtime.h>

#define TN 400
#define PN 4000
#define NBLOCKS 152       // one block per GB300 SM
#define TPB 800           // 25 warps x 16 targets = 400, all lanes active
#define MAXP 28           // >= ceil(PN/NBLOCKS)+1
#define ROW 72            // floats per pred row in shared

typedef unsigned long long ull;

__device__ __forceinline__ ull pk2(float lo, float hi) {
    ull r; asm("mov.b64 %0, {%1,%2};" : "=l"(r) : "f"(lo), "f"(hi)); return r;
}
__device__ __forceinline__ float2 u2f2(ull v) {
    float2 f; asm("mov.b64 {%0,%1}, %2;" : "=f"(f.x), "=f"(f.y) : "l"(v)); return f;
}
__device__ __forceinline__ ull padd2(ull a, ull b) {
    ull r; asm("add.rn.f32x2 %0, %1, %2;" : "=l"(r) : "l"(a), "l"(b)); return r;
}

// ptile row layout (72 floats):
//  [ 0..17] Zp kp0..8 (x,y pairs)     [18..19] 0
//  [20..35] Zp kp9..16                [36..37] 0 (half1 9th kp slot)
//  [38..39] pad
//  [40..43] {cp0, cp1, p0-p1, spp}
//  [44..52] Vp[0..8]                  [53..55] pad
//  [56..63] Vp[9..16]                 [64] 0 (half1 9th Vp)  [65..71] pad

__global__ __launch_bounds__(TPB, 1)
void matcher_kernel(const float* __restrict__ logits,   // [PN,2]
                    const float* __restrict__ pkp,      // [PN,53]
                    const int*   __restrict__ tids,     // [TN]
                    const float* __restrict__ tkp,      // [TN,53]
                    const int*   __restrict__ nbp,      // scalar num_boxes
                    float*       __restrict__ out)      // [PN,TN]
{
    __shared__ __align__(16) float ptile[MAXP * ROW];

    const int b = blockIdx.x;
    const int pbase = (b * PN) / NBLOCKS;
    const int npred = ((b + 1) * PN) / NBLOCKS - pbase;
    const int tid  = threadIdx.x;
    const int wr   = tid >> 5;
    const int lane = tid & 31;
    const int h    = lane >> 4;              // keypoint half
    const int tw   = (wr << 4) | (lane & 15);  // target 0..399, always valid

    int nbi = *nbp;
    float nb = (nbi > 0 && nbi < (1 << 20)) ? (float)nbi : *(const float*)nbp;
    const float inb = 1.0f / nb;

    // ---- pred preprocessing into shared (threads 0..npred-1, once) ----
    if (tid < npred) {
        const int gp = pbase + tid;
        const float l0 = logits[gp * 2 + 0];
        const float l1 = logits[gp * 2 + 1];
        const float m  = fmaxf(l0, l1);
        const float e0 = __expf(l0 - m);
        const float e1 = __expf(l1 - m);
        const float inv = 1.0f / (e0 + e1);
        const float p0 = e0 * inv, p1 = e1 * inv;

        const float* kp = pkp + gp * 53;
        const float c0 = kp[0], c1 = kp[1];
        float* sp = ptile + tid * ROW;
        #pragma unroll
        for (int k = 0; k < 18; ++k) sp[k] = kp[2 + k];          // kp0..8
        sp[18] = 0.0f; sp[19] = 0.0f;
        #pragma unroll
        for (int k = 0; k < 16; ++k) sp[20 + k] = kp[20 + k];    // kp9..16
        sp[36] = 0.0f; sp[37] = 0.0f; sp[38] = 0.0f; sp[39] = 0.0f;
        float sv = 0.0f;
        #pragma unroll
        for (int j = 0; j < 17; ++j) { float v = kp[36 + j]; sv = fmaf(v, v, sv); }
        sp[40] = c0;
        sp[41] = c1;
        sp[42] = p0 - p1;
        sp[43] = 0.2f * inb * sv + 0.5f * inb * (c0 * c0 + c1 * c1) - p0;  // spp
        #pragma unroll
        for (int j = 0; j < 9; ++j) sp[44 + j] = kp[36 + j];     // Vp0..8
        sp[53] = 0.0f; sp[54] = 0.0f; sp[55] = 0.0f;
        #pragma unroll
        for (int j = 0; j < 8; ++j) sp[56 + j] = kp[45 + j];     // Vp9..16
        #pragma unroll
        for (int j = 64; j < 72; ++j) sp[j] = 0.0f;
    }

    // ---- per-thread target state (9 keypoints of one half) ----
    const float* tk = tkp + tw * 53;
    const float cg0 = tk[0], cg1 = tk[1];
    const int jb  = h ? 9 : 0;
    const int cnt = h ? 8 : 9;
    ull   nzg[9];
    float w[9];
    #pragma unroll
    for (int i = 0; i < 9; ++i) {
        const int j = jb + i;
        const bool ok = (i < cnt);
        nzg[i] = ok ? pk2(-tk[2 + 2 * j], -tk[3 + 2 * j]) : 0ULL;
        w[i]   = ok ? 0.5f * inb * tk[36 + j] : 0.0f;
    }
    const float ncgx = -cg0, ncgy = -cg1;
    float tcx = 0.0f, tcy = 0.0f, idf = 0.0f, sgt = 0.0f, cflag = 0.0f;
    if (h == 0) {
        float sv = 0.0f;
        #pragma unroll
        for (int j = 0; j < 17; ++j) { float v = tk[36 + j]; sv = fmaf(v, v, sv); }
        sgt = 0.2f * inb * sv + 0.5f * inb * (cg0 * cg0 + cg1 * cg1);
        tcx = -inb * cg0;
        tcy = -inb * cg1;
        idf = (float)tids[tw];
        cflag = 1.0f;
    }
    __syncthreads();

    const int zbase = h ? 10 : 0;       // ull index of this half's Zp
    const int vbase = 44 + h * 12;      // float index of this half's Vp
    const bool doStore = (h == 0);

    auto compute = [&](const float* pp) -> float {
        const float4 h4 = *(const float4*)(pp + 40);   // cp0, cp1, p0-p1, spp
        const ull dc2 = pk2(h4.x + ncgx, h4.y + ncgy); // (Cp-Cg) per axis

        const ull* zb = (const ull*)pp + zbase;
        ull zz[9];
        {
            const ulonglong2* z2 = (const ulonglong2*)zb;
            ulonglong2 a = z2[0], c = z2[1], d = z2[2], e = z2[3];   // LDS.128 x4
            zz[0] = a.x; zz[1] = a.y; zz[2] = c.x; zz[3] = c.y;
            zz[4] = d.x; zz[5] = d.y; zz[6] = e.x; zz[7] = e.y;
            zz[8] = zb[8];                                            // LDS.64
        }

        float s = 0.0f, s8 = 0.0f;
        #pragma unroll
        for (int i = 0; i < 9; ++i) {
            ull dz = padd2(zz[i], nzg[i]);     // Zp - Zg (both axes)
            ull t  = padd2(dz, dc2);           // + (Cp - Cg)
            float2 d = u2f2(dz), u = u2f2(t);
            s  = fmaf(fabsf(d.x) + fabsf(d.y), w[i], s);
            s8 = fmaf(fabsf(u.x) + fabsf(u.y), w[i], s8);
        }

        const float* vb = pp + vbase;
        const float4 v0 = *(const float4*)vb;
        const float4 v1 = *(const float4*)(vb + 4);
        const float  v8 = vb[8];
        float dv = v0.x * w[0];
        dv = fmaf(v0.y, w[1], dv); dv = fmaf(v0.z, w[2], dv);
        dv = fmaf(v0.w, w[3], dv); dv = fmaf(v1.x, w[4], dv);
        dv = fmaf(v1.y, w[5], dv); dv = fmaf(v1.z, w[6], dv);
        dv = fmaf(v1.w, w[7], dv); dv = fmaf(v8,   w[8], dv);

        float res = fmaf(s8, 8.0f, s);        // 0.5*offset + 4*abs (w pre-scaled)
        res = fmaf(dv, -0.8f, res);           // viz cross
        res = fmaf(h4.x, tcx, res);           // center cross x (half0 only)
        res = fmaf(h4.y, tcy, res);           // center cross y
        res = fmaf(h4.z, idf, res);           // class id*(p0-p1)
        res = fmaf(h4.w, cflag, res);         // pred constant (incl -p0)
        return res + sgt;                     // target constant
    };

    int p = 0;
    for (; p + 1 < npred; p += 2) {
        float r0 = compute(ptile + p * ROW);
        float r1 = compute(ptile + (p + 1) * ROW);
        r0 += __shfl_xor_sync(0xffffffffu, r0, 16);
        r1 += __shfl_xor_sync(0xffffffffu, r1, 16);
        if (doStore) {
            out[(size_t)(pbase + p) * TN + tw]     = r0;
            out[(size_t)(pbase + p + 1) * TN + tw] = r1;
        }
    }
    if (p < npred) {
        float r0 = compute(ptile + p * ROW);
        r0 += __shfl_xor_sync(0xffffffffu, r0, 16);
        if (doStore)
            out[(size_t)(pbase + p) * TN + tw] = r0;
    }
}

extern "C" void kernel_launch(void* const* d_in, const int* in_sizes, int n_in,
                              void* d_out, int out_size)
{
    const float* logits = (const float*)d_in[0];   // pred_logits   [8,500,2]
    const float* pkp    = (const float*)d_in[1];   // pred_keypoints[8,500,53]
    const int*   tids   = (const int*)  d_in[2];   // tgt_ids       [400]
    const float* tkp    = (const float*)d_in[3];   // tgt_keypoints [400,53]
    const int*   nbp    = (const int*)  d_in[4];   // num_boxes scalar
    (void)in_sizes; (void)n_in; (void)out_size;

    matcher_kernel<<<NBLOCKS, TPB>>>(logits, pkp, tids, tkp, nbp, (float*)d_out);
}